// round 13
// baseline (speedup 1.0000x reference)
#include <cuda_runtime.h>
#include <cuda_bf16.h>
#include <math.h>
#include <stdint.h>

#define BB 32
#define TT 64
#define HH 1024
#define VV 32000
#define G3H 3072
#define MROWS 2048  // TT*BB

// ---------------------------------------------------------------------------
// Static device scratch
// ---------------------------------------------------------------------------
__device__ float g_GI[(size_t)MROWS * G3H];        // input gates, 25 MB
__device__ float g_Hist[(size_t)TT * BB * HH];     // hidden history, 8 MB
__device__ float g_lse[MROWS];                     // per-row logsumexp
__device__ float g_HT[2][(size_t)HH * BB];         // transposed h ping-pong, 2x128KB

__device__ __nv_bfloat16 g_Abf[(size_t)MROWS * HH];  // bf16 hidden history
__device__ __nv_bfloat16 g_Wbf[(size_t)VV * HH];     // bf16 fc_w

// ---------------------------------------------------------------------------
// Helpers
// ---------------------------------------------------------------------------
__device__ __forceinline__ uint32_t smem_u32(const void* p) {
    uint32_t a;
    asm("{ .reg .u64 t; cvta.to.shared.u64 t, %1; cvt.u32.u64 %0, t; }" : "=r"(a) : "l"(p));
    return a;
}
#define CP_ASYNC16(dst, src) \
    asm volatile("cp.async.cg.shared.global [%0], [%1], 16;" :: "r"(dst), "l"(src))
#define CP_COMMIT() asm volatile("cp.async.commit_group;" ::: "memory")
#define CP_WAIT(n)  asm volatile("cp.async.wait_group %0;" :: "n"(n) : "memory")

__device__ __forceinline__ void ldmatrix_x4(uint32_t& r0, uint32_t& r1,
                                            uint32_t& r2, uint32_t& r3, uint32_t addr)
{
    asm volatile("ldmatrix.sync.aligned.m8n8.x4.shared.b16 {%0,%1,%2,%3}, [%4];"
                 : "=r"(r0), "=r"(r1), "=r"(r2), "=r"(r3) : "r"(addr));
}
__device__ __forceinline__ void mma_bf16(float* c, const uint32_t* a, const uint32_t* b)
{
    asm volatile(
        "mma.sync.aligned.m16n8k16.row.col.f32.bf16.bf16.f32 "
        "{%0,%1,%2,%3}, {%4,%5,%6,%7}, {%8,%9}, {%0,%1,%2,%3};"
        : "+f"(c[0]), "+f"(c[1]), "+f"(c[2]), "+f"(c[3])
        : "r"(a[0]), "r"(a[1]), "r"(a[2]), "r"(a[3]), "r"(b[0]), "r"(b[1]));
}

// ---------------------------------------------------------------------------
// hmma_gemm (unchanged from R10): C = A bf16 @ B bf16^T + bias, fp32 accum.
// ---------------------------------------------------------------------------
#define HM_SMEM (65536 + 1024)

__global__ __launch_bounds__(256) void hmma_gemm_kernel(
    const __nv_bfloat16* __restrict__ A, const __nv_bfloat16* __restrict__ B,
    const float* __restrict__ bias, float* __restrict__ outp,
    int remap, int Nstride)
{
    extern __shared__ char smem_raw[];
    uint32_t base = (smem_u32(smem_raw) + 1023u) & ~1023u;

    int tid  = threadIdx.x;
    int warp = tid >> 5;
    int lane = tid & 31;
    int m0 = blockIdx.x * 128;
    int n0 = blockIdx.y * 128;

    int wm = warp & 1;
    int wn = warp >> 1;

    int lrow = tid & 127;
    int lsel = tid >> 7;
    const __nv_bfloat16* grow_ptr =
        lsel ? (B + (size_t)(n0 + lrow) * HH) : (A + (size_t)(m0 + lrow) * HH);
    uint32_t sdst_row = (uint32_t)lsel * 16384u + (uint32_t)lrow * 128u;
    uint32_t slot_xor = (uint32_t)(lrow & 7) * 16u;

    int a_r[4], b_r[2];
    #pragma unroll
    for (int mi = 0; mi < 4; mi++) a_r[mi] = wm * 64 + mi * 16 + (lane & 15);
    #pragma unroll
    for (int nh = 0; nh < 2; nh++)
        b_r[nh] = wn * 32 + nh * 16 + ((lane >> 4) << 3) + (lane & 7);
    int a_csel = lane >> 4;
    int b_csel = (lane >> 3) & 1;

    float acc[4][4][4];
    #pragma unroll
    for (int mi = 0; mi < 4; mi++)
        #pragma unroll
        for (int ni = 0; ni < 4; ni++)
            #pragma unroll
            for (int q = 0; q < 4; q++) acc[mi][ni][q] = 0.f;

    {
        const char* src = (const char*)grow_ptr;
        #pragma unroll
        for (int s = 0; s < 8; s++)
            CP_ASYNC16(base + sdst_row + (((uint32_t)s * 16u) ^ slot_xor), src + s * 16);
        CP_COMMIT();
    }

    for (int it = 0; it < 16; it++) {
        int buf = it & 1;
        if (it + 1 < 16) {
            const char* src = (const char*)(grow_ptr + (it + 1) * 64);
            uint32_t dst = base + (uint32_t)((it + 1) & 1) * 32768u + sdst_row;
            #pragma unroll
            for (int s = 0; s < 8; s++)
                CP_ASYNC16(dst + (((uint32_t)s * 16u) ^ slot_xor), src + s * 16);
            CP_COMMIT();
            CP_WAIT(1);
        } else {
            CP_WAIT(0);
        }
        __syncthreads();

        uint32_t abuf = base + (uint32_t)buf * 32768u;
        uint32_t bbuf = abuf + 16384u;

        #pragma unroll
        for (int k16 = 0; k16 < 4; k16++) {
            uint32_t af[4][4], bf[4][2];
            #pragma unroll
            for (int mi = 0; mi < 4; mi++) {
                int r = a_r[mi];
                uint32_t c16 = (uint32_t)(k16 * 2 + a_csel);
                uint32_t addr = abuf + (uint32_t)r * 128u + ((c16 ^ (uint32_t)(r & 7)) << 4);
                ldmatrix_x4(af[mi][0], af[mi][1], af[mi][2], af[mi][3], addr);
            }
            #pragma unroll
            for (int nh = 0; nh < 2; nh++) {
                int r = b_r[nh];
                uint32_t c16 = (uint32_t)(k16 * 2 + b_csel);
                uint32_t addr = bbuf + (uint32_t)r * 128u + ((c16 ^ (uint32_t)(r & 7)) << 4);
                ldmatrix_x4(bf[nh * 2][0], bf[nh * 2][1],
                            bf[nh * 2 + 1][0], bf[nh * 2 + 1][1], addr);
            }
            #pragma unroll
            for (int mi = 0; mi < 4; mi++)
                #pragma unroll
                for (int ni = 0; ni < 4; ni++)
                    mma_bf16(acc[mi][ni], af[mi], bf[ni]);
        }
        __syncthreads();
    }

    int g  = lane >> 2;
    int qc = (lane & 3) * 2;
    #pragma unroll
    for (int mi = 0; mi < 4; mi++) {
        int grow = m0 + wm * 64 + mi * 16 + g;
        #pragma unroll
        for (int ni = 0; ni < 4; ni++) {
            int gcol = n0 + wn * 32 + ni * 8 + qc;
            float bx = bias[gcol], by = bias[gcol + 1];
            int r1 = grow, r2 = grow + 8;
            size_t o1, o2;
            if (remap) {
                o1 = (size_t)((r1 & 31) * TT + (r1 >> 5)) * (size_t)Nstride;
                o2 = (size_t)((r2 & 31) * TT + (r2 >> 5)) * (size_t)Nstride;
            } else {
                o1 = (size_t)r1 * (size_t)Nstride;
                o2 = (size_t)r2 * (size_t)Nstride;
            }
            float2 v1 = make_float2(acc[mi][ni][0] + bx, acc[mi][ni][1] + by);
            float2 v2 = make_float2(acc[mi][ni][2] + bx, acc[mi][ni][3] + by);
            *(float2*)(outp + o1 + gcol) = v1;
            *(float2*)(outp + o2 + gcol) = v2;
        }
    }
}

// ---------------------------------------------------------------------------
// fp32 -> bf16 convert
// ---------------------------------------------------------------------------
__global__ __launch_bounds__(256) void tobf16_kernel(
    const float* __restrict__ src, __nv_bfloat16* __restrict__ dst)
{
    size_t i = (size_t)blockIdx.x * 256 + threadIdx.x;
    float4 v = ((const float4*)src)[i];
    __nv_bfloat162* d2 = (__nv_bfloat162*)(dst + i * 4);
    d2[0] = __nv_bfloat162(__float2bfloat16(v.x), __float2bfloat16(v.y));
    d2[1] = __nv_bfloat162(__float2bfloat16(v.z), __float2bfloat16(v.w));
}

// ---------------------------------------------------------------------------
// GI = relu(emb[tok]) @ W_ih^T + b_ih  (fp32 sgemm, exact)
// ---------------------------------------------------------------------------
__global__ __launch_bounds__(256) void gi_gemm_kernel(
    const int* __restrict__ target,
    const float* __restrict__ emb,
    const float* __restrict__ W_ih,
    const float* __restrict__ b_ih)
{
    __shared__ float As[8][132];
    __shared__ float Bs[8][132];
    int tid = threadIdx.x;
    int bm = blockIdx.y * 128;
    int bn = blockIdx.x * 128;

    int a_row = tid >> 1;
    int a_k4 = (tid & 1) << 2;

    int m = bm + a_row;
    int t = m >> 5;
    int b = m & 31;
    int tok = (t == 0) ? 0 : target[b * TT + t - 1];
    const float* Arow = emb + (size_t)tok * HH + a_k4;
    const float* Brow = W_ih + (size_t)(bn + a_row) * HH + a_k4;

    int tx = tid & 15, ty = tid >> 4;
    float acc[8][8];
    #pragma unroll
    for (int i = 0; i < 8; i++)
        #pragma unroll
        for (int j = 0; j < 8; j++) acc[i][j] = 0.f;

    for (int k0 = 0; k0 < HH; k0 += 8) {
        float4 av = *(const float4*)(Arow + k0);
        float4 bv = *(const float4*)(Brow + k0);
        av.x = fmaxf(av.x, 0.f); av.y = fmaxf(av.y, 0.f);
        av.z = fmaxf(av.z, 0.f); av.w = fmaxf(av.w, 0.f);
        __syncthreads();
        As[a_k4 + 0][a_row] = av.x;
        As[a_k4 + 1][a_row] = av.y;
        As[a_k4 + 2][a_row] = av.z;
        As[a_k4 + 3][a_row] = av.w;
        Bs[a_k4 + 0][a_row] = bv.x;
        Bs[a_k4 + 1][a_row] = bv.y;
        Bs[a_k4 + 2][a_row] = bv.z;
        Bs[a_k4 + 3][a_row] = bv.w;
        __syncthreads();
        #pragma unroll
        for (int kk = 0; kk < 8; kk++) {
            float a[8], bb[8];
            *(float4*)&a[0]  = *(const float4*)&As[kk][ty * 8];
            *(float4*)&a[4]  = *(const float4*)&As[kk][ty * 8 + 4];
            *(float4*)&bb[0] = *(const float4*)&Bs[kk][tx * 8];
            *(float4*)&bb[4] = *(const float4*)&Bs[kk][tx * 8 + 4];
            #pragma unroll
            for (int i = 0; i < 8; i++)
                #pragma unroll
                for (int j = 0; j < 8; j++)
                    acc[i][j] += a[i] * bb[j];
        }
    }

    #pragma unroll
    for (int i = 0; i < 8; i++) {
        int mm = bm + ty * 8 + i;
        float* dst = g_GI + (size_t)mm * G3H + bn + tx * 8;
        #pragma unroll
        for (int j = 0; j < 8; j += 4) {
            float4 v;
            v.x = acc[i][j + 0] + b_ih[bn + tx * 8 + j + 0];
            v.y = acc[i][j + 1] + b_ih[bn + tx * 8 + j + 1];
            v.z = acc[i][j + 2] + b_ih[bn + tx * 8 + j + 2];
            v.w = acc[i][j + 3] + b_ih[bn + tx * 8 + j + 3];
            *(float4*)(dst + j) = v;
        }
    }
}

// ---------------------------------------------------------------------------
// Transpose enc_hidden into HT buffer 0 (once, before the recurrence).
// ---------------------------------------------------------------------------
__global__ __launch_bounds__(256) void transpose_h0_kernel(const float* __restrict__ enc)
{
    int i = blockIdx.x * 256 + threadIdx.x;   // 0..32767
    int b = i >> 10, j = i & 1023;
    g_HT[0][(size_t)j * BB + b] = enc[i];
}

// ---------------------------------------------------------------------------
// FUSED GRU step: one kernel computes gh (all 3 gates) for 8 hidden columns
// per block across full K, then applies the GRU nonlinearity in-place.
// grid = 128 blocks (8 cols each), block = 256 (warp w -> column j0+w).
// h kept transposed in g_HT ping-pong (read t&1, write (t+1)&1).
// Double-buffered cp.async for both W (24 rows x 64k) and hT (64k x 32b).
// ---------------------------------------------------------------------------
#define KC 64

__global__ __launch_bounds__(256) void gru_fused_kernel(
    const float* __restrict__ W_hh, const float* __restrict__ b_hh, int t)
{
    __shared__ float hsm[2][KC][32];    // [buf][k][batch], conflict-free rows
    __shared__ float wsm[2][24][KC];    // [buf][gate*8+w][k]

    int tid  = threadIdx.x;
    int warp = tid >> 5;
    int lane = tid & 31;                // batch
    int j0 = blockIdx.x * 8;

    const float* Tread = g_HT[t & 1];
    float*       Twrite = g_HT[(t + 1) & 1];

    uint32_t hs_base = smem_u32(&hsm[0][0][0]);
    uint32_t ws_base = smem_u32(&wsm[0][0][0]);

    float ar = 0.f, az = 0.f, an = 0.f;

    // chunk issue: 512 h units (16B) + 384 W units
    #define GRU_ISSUE(c, buf) do { \
        uint32_t hdst = hs_base + (uint32_t)(buf) * (KC * 32 * 4); \
        uint32_t wdst = ws_base + (uint32_t)(buf) * (24 * KC * 4); \
        _Pragma("unroll") \
        for (int u0 = 0; u0 < 896; u0 += 256) { \
            int u = u0 + tid; \
            if (u < 512) { \
                int k = u >> 3, q = u & 7; \
                CP_ASYNC16(hdst + (uint32_t)(k * 128 + q * 16), \
                    (const char*)(Tread + (size_t)((c) * KC + k) * BB + q * 4)); \
            } else if (u < 896) { \
                int uu = u - 512; int rr = uu >> 4, s = uu & 15; \
                int gate = rr >> 3, wc = rr & 7; \
                CP_ASYNC16(wdst + (uint32_t)(rr * KC * 4 + s * 16), \
                    (const char*)(W_hh + (size_t)(gate * 1024 + j0 + wc) * HH + (c) * KC + s * 4)); \
            } \
        } \
        CP_COMMIT(); \
    } while (0)

    GRU_ISSUE(0, 0);

    for (int c = 0; c < 16; c++) {
        int buf = c & 1;
        if (c + 1 < 16) {
            GRU_ISSUE(c + 1, (c + 1) & 1);
            CP_WAIT(1);
        } else {
            CP_WAIT(0);
        }
        __syncthreads();

        #pragma unroll
        for (int k4 = 0; k4 < KC / 4; k4++) {
            float h0 = hsm[buf][k4 * 4 + 0][lane];
            float h1 = hsm[buf][k4 * 4 + 1][lane];
            float h2 = hsm[buf][k4 * 4 + 2][lane];
            float h3 = hsm[buf][k4 * 4 + 3][lane];
            float4 wr = *(const float4*)&wsm[buf][warp][k4 * 4];
            float4 wz = *(const float4*)&wsm[buf][8 + warp][k4 * 4];
            float4 wn = *(const float4*)&wsm[buf][16 + warp][k4 * 4];
            ar += wr.x * h0 + wr.y * h1 + wr.z * h2 + wr.w * h3;
            az += wz.x * h0 + wz.y * h1 + wz.z * h2 + wz.w * h3;
            an += wn.x * h0 + wn.y * h1 + wn.z * h2 + wn.w * h3;
        }
        __syncthreads();
    }

    // epilogue: GRU combine for (batch=lane, col=j)
    int j = j0 + warp;
    float gr = ar + b_hh[j];
    float gz = az + b_hh[HH + j];
    float gn = an + b_hh[2 * HH + j];

    const float* gi = g_GI + (size_t)(t * BB + lane) * G3H;
    float ir  = gi[j];
    float iz  = gi[HH + j];
    float inn = gi[2 * HH + j];

    float r = 1.f / (1.f + expf(-(ir + gr)));
    float z = 1.f / (1.f + expf(-(iz + gz)));
    float n = tanhf(inn + r * gn);
    float ho = Tread[(size_t)j * BB + lane];
    float hn = (1.f - z) * n + z * ho;

    Twrite[(size_t)j * BB + lane] = hn;
    g_Hist[(size_t)t * BB * HH + (size_t)lane * HH + j] = hn;
    #undef GRU_ISSUE
}

// ---------------------------------------------------------------------------
// log_softmax + final hidden
// ---------------------------------------------------------------------------
__global__ __launch_bounds__(256) void rowstats_kernel(const float* __restrict__ out)
{
    int r = blockIdx.x;
    const float* row = out + (size_t)r * VV;
    int tid = threadIdx.x;
    float m = -1e30f, s = 0.f;
    for (int i = tid; i < VV; i += 256) {
        float x = row[i];
        if (x > m) { s = s * expf(m - x) + 1.f; m = x; }
        else       { s += expf(x - m); }
    }
    __shared__ float sm[256], ss[256];
    sm[tid] = m; ss[tid] = s;
    __syncthreads();
    for (int off = 128; off > 0; off >>= 1) {
        if (tid < off) {
            float m1 = sm[tid], s1 = ss[tid];
            float m2 = sm[tid + off], s2 = ss[tid + off];
            float mm = fmaxf(m1, m2);
            sm[tid] = mm;
            ss[tid] = s1 * expf(m1 - mm) + s2 * expf(m2 - mm);
        }
        __syncthreads();
    }
    if (tid == 0) g_lse[r] = sm[0] + logf(ss[0]);
}

__global__ __launch_bounds__(256) void finalize_kernel(float* __restrict__ out)
{
    unsigned g = blockIdx.x * 256u + threadIdx.x;
    unsigned r = (g * 4u) / (unsigned)VV;
    float l = g_lse[r];
    float4 v = reinterpret_cast<float4*>(out)[g];
    v.x -= l; v.y -= l; v.z -= l; v.w -= l;
    reinterpret_cast<float4*>(out)[g] = v;
}

__global__ __launch_bounds__(256) void copy_hidden_kernel(float* __restrict__ out)
{
    int i = blockIdx.x * 256 + threadIdx.x;
    out[(size_t)BB * TT * VV + i] = g_Hist[(size_t)(TT - 1) * BB * HH + i];
}

// ---------------------------------------------------------------------------
extern "C" void kernel_launch(void* const* d_in, const int* in_sizes, int n_in,
                              void* d_out, int out_size)
{
    (void)in_sizes; (void)n_in; (void)out_size;
    const float* enc_hidden = (const float*)d_in[1];
    const int*   target     = (const int*)d_in[2];
    const float* emb        = (const float*)d_in[3];
    const float* W_ih       = (const float*)d_in[4];
    const float* W_hh       = (const float*)d_in[5];
    const float* b_ih       = (const float*)d_in[6];
    const float* b_hh       = (const float*)d_in[7];
    const float* fc_w       = (const float*)d_in[8];
    const float* fc_b       = (const float*)d_in[9];
    float* out = (float*)d_out;

    cudaFuncSetAttribute(hmma_gemm_kernel,
                         cudaFuncAttributeMaxDynamicSharedMemorySize, HM_SMEM);

    void *pAbf, *pWbf, *pHist;
    cudaGetSymbolAddress(&pAbf, g_Abf);
    cudaGetSymbolAddress(&pWbf, g_Wbf);
    cudaGetSymbolAddress(&pHist, g_Hist);

    // Phase 0: fc_w -> bf16
    tobf16_kernel<<<(VV * HH / 4) / 256, 256>>>(fc_w, (__nv_bfloat16*)pWbf);

    // Phase 1: GI = relu(emb[tok]) @ W_ih^T + b_ih  (fp32, exact)
    gi_gemm_kernel<<<dim3(G3H / 128, MROWS / 128), 256>>>(target, emb, W_ih, b_ih);

    // Phase 2: sequential recurrence — ONE fused kernel per step
    transpose_h0_kernel<<<(BB * HH) / 256, 256>>>(enc_hidden);
    for (int t = 0; t < TT; t++)
        gru_fused_kernel<<<128, 256>>>(W_hh, b_hh, t);

    // Phase 3: Hist -> bf16, then FC on tensor cores
    tobf16_kernel<<<(MROWS * HH / 4) / 256, 256>>>((const float*)pHist,
                                                   (__nv_bfloat16*)pAbf);
    hmma_gemm_kernel<<<dim3(MROWS / 128, VV / 128), 256, HM_SMEM>>>(
        (const __nv_bfloat16*)pAbf, (const __nv_bfloat16*)pWbf,
        fc_b, out, 1, VV);

    // Phase 4: log_softmax in-place
    rowstats_kernel<<<MROWS, 256>>>(out);
    finalize_kernel<<<(BB * TT * VV / 4) / 256, 256>>>(out);

    // Phase 5: final hidden state
    copy_hidden_kernel<<<(BB * HH) / 256, 256>>>(out);
}